// round 10
// baseline (speedup 1.0000x reference)
#include <cuda_runtime.h>

// Convolution_22600117912286: continuous convolution with Gaussian radial basis.
// out[z,a,i] = (1/sqrt(n_norm)) * sum_b sum_c exp(-((d_ab - c*w)/w)^2) * G[z,b,c,i]
//   where G[z,b,c,i] = sum_j W[c,i,j] * features[z,b,j]
// Shapes: B=2, N=1024, D_IN=8, D_OUT=8, C=32, R_MAX=3.5, w=3.5/31.
//
// R6 changes vs R4:
//  - prep_G rewritten: W row in registers, features broadcast via smem,
//    fully coalesced stores (was 21.2us latency-bound -> ~2.5us).
//  - SPLIT 4->8: 512 blocks, wave imbalance 2.0 -> 1.33.
//  - k-window padded with zero rows (-4..35): no predicates in tap loop.
//  - packed fma.rn.f32x2 accumulators: 72 scalar FFMA/pair -> 36 FFMA2.

#define BATCH   2
#define NPTS    1024
#define DIN     8
#define DOUT    8
#define NC      32
#define RMAXF   3.5f
#define TILE_A  32
#define SPLIT   8
#define B_TILE  16
#define KPAD    4
#define KROWS   (NC + 2 * KPAD)   // 40 rows of k per b (rows 0..3 and 36..39 are zero)
#define GSTRIDE 12                // floats per (b,k) row: 8 data + 4 pad = 48B

// scratch (no allocations allowed -> __device__ globals)
__device__ float g_G[BATCH * NPTS * NC * DOUT];                 // 2 MB
__device__ float g_partial[SPLIT * BATCH * NPTS * DOUT];        // 512 KB

// packed f32x2 helpers (FFMA2: not emittable from plain C++, PTX only)
__device__ __forceinline__ void ffma2(unsigned long long& acc,
                                      unsigned long long g,
                                      unsigned long long w)
{
    asm("fma.rn.f32x2 %0, %1, %2, %0;" : "+l"(acc) : "l"(g), "l"(w));
}
__device__ __forceinline__ unsigned long long pack2(float v)
{
    unsigned long long r;
    asm("mov.b64 %0, {%1, %1};" : "=l"(r) : "r"(__float_as_int(v)));
    return r;
}

// ---------------------------------------------------------------------------
// Kernel 1: G[z,b,c,i] = scale * sum_j W[c,i,j] * f[z,b,j]
// Block = 32 zb rows x 256 output columns (c*8+i). W row lives in registers,
// features broadcast from smem, stores fully coalesced.
// ---------------------------------------------------------------------------
__global__ __launch_bounds__(256)
void prep_G_kernel(const float* __restrict__ feat,
                   const float* __restrict__ W,
                   const int* __restrict__ n_norm)
{
    __shared__ __align__(16) float sf[32 * DIN];    // 32 zb x 8 features

    const int tid = threadIdx.x;
    const int zb0 = blockIdx.x * 32;

    sf[tid] = feat[zb0 * DIN + tid];                // 256 floats, coalesced
    __syncthreads();

    const float scale = rsqrtf((float)(*n_norm));

    // this thread's output column co = c*8 + i; its W row is W[co*8 .. co*8+7]
    const float4 wa = *reinterpret_cast<const float4*>(W + tid * DIN);
    const float4 wb = *reinterpret_cast<const float4*>(W + tid * DIN + 4);
    const float w0 = wa.x * scale, w1 = wa.y * scale, w2 = wa.z * scale, w3 = wa.w * scale;
    const float w4 = wb.x * scale, w5 = wb.y * scale, w6 = wb.z * scale, w7 = wb.w * scale;

#pragma unroll 8
    for (int b = 0; b < 32; ++b) {
        float4 fa = *reinterpret_cast<const float4*>(&sf[b * DIN]);      // broadcast
        float4 fb = *reinterpret_cast<const float4*>(&sf[b * DIN + 4]);
        float s = w0 * fa.x;
        s = fmaf(w1, fa.y, s);
        s = fmaf(w2, fa.z, s);
        s = fmaf(w3, fa.w, s);
        s = fmaf(w4, fb.x, s);
        s = fmaf(w5, fb.y, s);
        s = fmaf(w6, fb.z, s);
        s = fmaf(w7, fb.w, s);
        g_G[(size_t)(zb0 + b) * (NC * DOUT) + tid] = s;                  // coalesced
    }
}

// ---------------------------------------------------------------------------
// Kernel 2: main pairwise contraction.
// Block = (z, a-tile of 32, b-split of 128). Thread (a_local, lane_b).
// Gaussian basis via peak-anchored multiplicative recurrence over a +/-4
// center window; out-of-range taps read permanently-zero padded smem rows.
// ---------------------------------------------------------------------------
__global__ __launch_bounds__(256)
void conv_kernel(const float* __restrict__ geom)
{
    __shared__ __align__(16) float  sG[B_TILE * KROWS * GSTRIDE];  // 7680 f = 30 KB
    __shared__ float4 sgeo[B_TILE];

    const int tid     = threadIdx.x;
    const int z       = blockIdx.z;
    const int a0      = blockIdx.x * TILE_A;
    const int bsplit0 = blockIdx.y * (NPTS / SPLIT);
    const int a_local = tid & (TILE_A - 1);
    const int lane_b  = tid >> 5;                  // 0..7

    // zero the whole tile once; pad rows are never written afterwards
#pragma unroll
    for (int q = tid; q < B_TILE * KROWS * GSTRIDE; q += 256) sG[q] = 0.0f;

    const int   a  = a0 + a_local;
    const float ax = geom[(z * NPTS + a) * 3 + 0];
    const float ay = geom[(z * NPTS + a) * 3 + 1];
    const float az = geom[(z * NPTS + a) * 3 + 2];

    const float INV_W = (float)(NC - 1) / RMAXF;   // 31/3.5
    const float E2    = 0.13533528323661270f;      // exp(-2)

    unsigned long long A0 = 0ull, A1 = 0ull, A2 = 0ull, A3 = 0ull;

    const int NT = (NPTS / SPLIT) / B_TILE;        // 8 tiles
    for (int t = 0; t < NT; ++t) {
        const int bt = bsplit0 + t * B_TILE;
        __syncthreads();                           // protect sG/sgeo from last iter

        // --- stage geometry tile ---
        if (tid < B_TILE) {
            const float* gp = geom + (size_t)(z * NPTS + bt + tid) * 3;
            sgeo[tid] = make_float4(gp[0], gp[1], gp[2], 0.f);
        }
        // --- stage G tile: 16b x 32k x 8i, coalesced gmem -> padded smem ---
        const float4* src = reinterpret_cast<const float4*>(
            g_G + (size_t)((z * NPTS + bt) * NC) * DOUT);
#pragma unroll
        for (int it = 0; it < 4; ++it) {
            int q = tid + it * 256;                // 0..1023 float4s
            float4 v  = src[q];
            int   i4  = q & 1;
            int   k   = (q >> 1) & (NC - 1);
            int   bl  = q >> 6;
            *reinterpret_cast<float4*>(
                &sG[(bl * KROWS + k + KPAD) * GSTRIDE + i4 * 4]) = v;
        }
        __syncthreads();

#pragma unroll
        for (int half = 0; half < 2; ++half) {
            const int bl = lane_b + half * 8;
            float4 gb = sgeo[bl];
            float dx = ax - gb.x, dy = ay - gb.y, dz = az - gb.z;
            float d2 = fmaf(dx, dx, fmaf(dy, dy, fmaf(dz, dz, 1e-12f)));
            float u0 = sqrtf(d2) * INV_W;          // distance in width units
            int   k0 = __float2int_rn(u0);
            k0 = min(k0, NC - 1);                  // u0 >= 0 so k0 >= 0
            float p  = u0 - (float)k0;             // in [-0.5, 0.5] unless past last center
            float pc = fminf(p, 4.0f);
            float b0 = (p < 4.0f) ? __expf(-pc * pc) : 0.0f;
            float ru = __expf(fmaf( 2.0f, pc, -1.0f));
            float rd = __expf(fmaf(-2.0f, pc, -1.0f));

            // weights for centers k0-4 .. k0+4 (truncated terms <= exp(-12.25))
            float wgt[9];
            wgt[4] = b0;
            float bb = b0, r = ru;
#pragma unroll
            for (int s = 1; s <= 4; ++s) { bb *= r; r *= E2; wgt[4 + s] = bb; }
            bb = b0; r = rd;
#pragma unroll
            for (int s = 1; s <= 4; ++s) { bb *= r; r *= E2; wgt[4 - s] = bb; }

            const float* gbase = &sG[(bl * KROWS + k0 + KPAD - 4) * GSTRIDE];
#pragma unroll
            for (int s = 0; s < 9; ++s) {
                ulonglong2 gA = *reinterpret_cast<const ulonglong2*>(gbase + s * GSTRIDE);
                ulonglong2 gB = *reinterpret_cast<const ulonglong2*>(gbase + s * GSTRIDE + 4);
                unsigned long long wp = pack2(wgt[s]);
                ffma2(A0, gA.x, wp);
                ffma2(A1, gA.y, wp);
                ffma2(A2, gB.x, wp);
                ffma2(A3, gB.y, wp);
            }
        }
    }
    __syncthreads();                               // last tile's reads done

    // --- deterministic in-block reduction over the 8 lane_b partials ---
    float* sred = sG;                              // reuse smem (2048 floats needed)
    {
        ulonglong2* sp64 = reinterpret_cast<ulonglong2*>(sred);
        sp64[(a_local * 8 + lane_b) * 2 + 0] = make_ulonglong2(A0, A1);
        sp64[(a_local * 8 + lane_b) * 2 + 1] = make_ulonglong2(A2, A3);
    }
    __syncthreads();
    {
        int al = tid >> 3;          // 0..31
        int i  = tid & 7;           // 0..7
        float s = 0.0f;
#pragma unroll
        for (int lb = 0; lb < 8; ++lb)
            s += sred[(al * 8 + lb) * 8 + i];
        g_partial[((blockIdx.y * BATCH + z) * NPTS + (a0 + al)) * DOUT + i] = s;
    }
}

// ---------------------------------------------------------------------------
// Kernel 3: sum the SPLIT partials into the output (deterministic, no atomics)
// ---------------------------------------------------------------------------
__global__ __launch_bounds__(256)
void reduce_kernel(float* __restrict__ out)
{
    int t = blockIdx.x * blockDim.x + threadIdx.x;
    if (t < BATCH * NPTS * DOUT) {
        float s = 0.0f;
#pragma unroll
        for (int sp = 0; sp < SPLIT; ++sp)
            s += g_partial[sp * (BATCH * NPTS * DOUT) + t];
        out[t] = s;
    }
}

extern "C" void kernel_launch(void* const* d_in, const int* in_sizes, int n_in,
                              void* d_out, int out_size)
{
    const float* features = (const float*)d_in[0];   // [2,1024,8]
    const float* geometry = (const float*)d_in[1];   // [2,1024,3]
    const float* W        = (const float*)d_in[2];   // [32,8,8]
    const int*   n_norm   = (const int*)d_in[3];     // scalar
    float*       out      = (float*)d_out;           // [2,1024,8]

    prep_G_kernel<<<(BATCH * NPTS) / 32, 256>>>(features, W, n_norm);
    conv_kernel<<<dim3(NPTS / TILE_A, SPLIT, BATCH), 256>>>(geometry);
    reduce_kernel<<<(BATCH * NPTS * DOUT + 255) / 256, 256>>>(out);
}

// round 11
// speedup vs baseline: 1.0111x; 1.0111x over previous
#include <cuda_runtime.h>

// Convolution_22600117912286: continuous convolution with Gaussian radial basis.
// out[z,a,i] = (1/sqrt(n_norm)) * sum_b sum_c exp(-((d_ab - c*w)/w)^2) * G[z,b,c,i]
//   where G[z,b,c,i] = sum_j W[c,i,j] * features[z,b,j]
// Shapes: B=2, N=1024, D_IN=8, D_OUT=8, C=32, R_MAX=3.5, w=3.5/31.
//
// R6 changes vs R4:
//  - prep_G rewritten: W row in registers, features broadcast via smem,
//    fully coalesced stores (was 21.2us latency-bound -> ~2.5us).
//  - SPLIT 4->8: 512 blocks, wave imbalance 2.0 -> 1.33.
//  - k-window padded with zero rows (-4..35): no predicates in tap loop.
//  - packed fma.rn.f32x2 accumulators: 72 scalar FFMA/pair -> 36 FFMA2.

#define BATCH   2
#define NPTS    1024
#define DIN     8
#define DOUT    8
#define NC      32
#define RMAXF   3.5f
#define TILE_A  32
#define SPLIT   8
#define B_TILE  16
#define KPAD    4
#define KROWS   (NC + 2 * KPAD)   // 40 rows of k per b (rows 0..3 and 36..39 are zero)
#define GSTRIDE 12                // floats per (b,k) row: 8 data + 4 pad = 48B

// scratch (no allocations allowed -> __device__ globals)
__device__ float g_G[BATCH * NPTS * NC * DOUT];                 // 2 MB
__device__ float g_partial[SPLIT * BATCH * NPTS * DOUT];        // 512 KB

// packed f32x2 helpers (FFMA2: not emittable from plain C++, PTX only)
__device__ __forceinline__ void ffma2(unsigned long long& acc,
                                      unsigned long long g,
                                      unsigned long long w)
{
    asm("fma.rn.f32x2 %0, %1, %2, %0;" : "+l"(acc) : "l"(g), "l"(w));
}
__device__ __forceinline__ unsigned long long pack2(float v)
{
    unsigned long long r;
    asm("mov.b64 %0, {%1, %1};" : "=l"(r) : "r"(__float_as_int(v)));
    return r;
}

// ---------------------------------------------------------------------------
// Kernel 1: G[z,b,c,i] = scale * sum_j W[c,i,j] * f[z,b,j]
// Block = 32 zb rows x 256 output columns (c*8+i). W row lives in registers,
// features broadcast from smem, stores fully coalesced.
// ---------------------------------------------------------------------------
__global__ __launch_bounds__(256)
void prep_G_kernel(const float* __restrict__ feat,
                   const float* __restrict__ W,
                   const int* __restrict__ n_norm)
{
    __shared__ __align__(16) float sf[32 * DIN];    // 32 zb x 8 features

    const int tid = threadIdx.x;
    const int zb0 = blockIdx.x * 32;

    sf[tid] = feat[zb0 * DIN + tid];                // 256 floats, coalesced
    __syncthreads();

    const float scale = rsqrtf((float)(*n_norm));

    // this thread's output column co = c*8 + i; its W row is W[co*8 .. co*8+7]
    const float4 wa = *reinterpret_cast<const float4*>(W + tid * DIN);
    const float4 wb = *reinterpret_cast<const float4*>(W + tid * DIN + 4);
    const float w0 = wa.x * scale, w1 = wa.y * scale, w2 = wa.z * scale, w3 = wa.w * scale;
    const float w4 = wb.x * scale, w5 = wb.y * scale, w6 = wb.z * scale, w7 = wb.w * scale;

#pragma unroll 8
    for (int b = 0; b < 32; ++b) {
        float4 fa = *reinterpret_cast<const float4*>(&sf[b * DIN]);      // broadcast
        float4 fb = *reinterpret_cast<const float4*>(&sf[b * DIN + 4]);
        float s = w0 * fa.x;
        s = fmaf(w1, fa.y, s);
        s = fmaf(w2, fa.z, s);
        s = fmaf(w3, fa.w, s);
        s = fmaf(w4, fb.x, s);
        s = fmaf(w5, fb.y, s);
        s = fmaf(w6, fb.z, s);
        s = fmaf(w7, fb.w, s);
        g_G[(size_t)(zb0 + b) * (NC * DOUT) + tid] = s;                  // coalesced
    }
}

// ---------------------------------------------------------------------------
// Kernel 2: main pairwise contraction.
// Block = (z, a-tile of 32, b-split of 128). Thread (a_local, lane_b).
// Gaussian basis via peak-anchored multiplicative recurrence over a +/-4
// center window; out-of-range taps read permanently-zero padded smem rows.
// ---------------------------------------------------------------------------
__global__ __launch_bounds__(256)
void conv_kernel(const float* __restrict__ geom)
{
    __shared__ __align__(16) float  sG[B_TILE * KROWS * GSTRIDE];  // 7680 f = 30 KB
    __shared__ float4 sgeo[B_TILE];

    const int tid     = threadIdx.x;
    const int z       = blockIdx.z;
    const int a0      = blockIdx.x * TILE_A;
    const int bsplit0 = blockIdx.y * (NPTS / SPLIT);
    const int a_local = tid & (TILE_A - 1);
    const int lane_b  = tid >> 5;                  // 0..7

    // zero the whole tile once; pad rows are never written afterwards
#pragma unroll
    for (int q = tid; q < B_TILE * KROWS * GSTRIDE; q += 256) sG[q] = 0.0f;

    const int   a  = a0 + a_local;
    const float ax = geom[(z * NPTS + a) * 3 + 0];
    const float ay = geom[(z * NPTS + a) * 3 + 1];
    const float az = geom[(z * NPTS + a) * 3 + 2];

    const float INV_W = (float)(NC - 1) / RMAXF;   // 31/3.5
    const float E2    = 0.13533528323661270f;      // exp(-2)

    unsigned long long A0 = 0ull, A1 = 0ull, A2 = 0ull, A3 = 0ull;

    const int NT = (NPTS / SPLIT) / B_TILE;        // 8 tiles
    for (int t = 0; t < NT; ++t) {
        const int bt = bsplit0 + t * B_TILE;
        __syncthreads();                           // protect sG/sgeo from last iter

        // --- stage geometry tile ---
        if (tid < B_TILE) {
            const float* gp = geom + (size_t)(z * NPTS + bt + tid) * 3;
            sgeo[tid] = make_float4(gp[0], gp[1], gp[2], 0.f);
        }
        // --- stage G tile: 16b x 32k x 8i, coalesced gmem -> padded smem ---
        const float4* src = reinterpret_cast<const float4*>(
            g_G + (size_t)((z * NPTS + bt) * NC) * DOUT);
#pragma unroll
        for (int it = 0; it < 4; ++it) {
            int q = tid + it * 256;                // 0..1023 float4s
            float4 v  = src[q];
            int   i4  = q & 1;
            int   k   = (q >> 1) & (NC - 1);
            int   bl  = q >> 6;
            *reinterpret_cast<float4*>(
                &sG[(bl * KROWS + k + KPAD) * GSTRIDE + i4 * 4]) = v;
        }
        __syncthreads();

#pragma unroll
        for (int half = 0; half < 2; ++half) {
            const int bl = lane_b + half * 8;
            float4 gb = sgeo[bl];
            float dx = ax - gb.x, dy = ay - gb.y, dz = az - gb.z;
            float d2 = fmaf(dx, dx, fmaf(dy, dy, fmaf(dz, dz, 1e-12f)));
            float u0 = sqrtf(d2) * INV_W;          // distance in width units
            int   k0 = __float2int_rn(u0);
            k0 = min(k0, NC - 1);                  // u0 >= 0 so k0 >= 0
            float p  = u0 - (float)k0;             // in [-0.5, 0.5] unless past last center
            float pc = fminf(p, 4.0f);
            float b0 = (p < 4.0f) ? __expf(-pc * pc) : 0.0f;
            float ru = __expf(fmaf( 2.0f, pc, -1.0f));
            float rd = __expf(fmaf(-2.0f, pc, -1.0f));

            // weights for centers k0-4 .. k0+4 (truncated terms <= exp(-12.25))
            float wgt[9];
            wgt[4] = b0;
            float bb = b0, r = ru;
#pragma unroll
            for (int s = 1; s <= 4; ++s) { bb *= r; r *= E2; wgt[4 + s] = bb; }
            bb = b0; r = rd;
#pragma unroll
            for (int s = 1; s <= 4; ++s) { bb *= r; r *= E2; wgt[4 - s] = bb; }

            const float* gbase = &sG[(bl * KROWS + k0 + KPAD - 4) * GSTRIDE];
#pragma unroll
            for (int s = 0; s < 9; ++s) {
                ulonglong2 gA = *reinterpret_cast<const ulonglong2*>(gbase + s * GSTRIDE);
                ulonglong2 gB = *reinterpret_cast<const ulonglong2*>(gbase + s * GSTRIDE + 4);
                unsigned long long wp = pack2(wgt[s]);
                ffma2(A0, gA.x, wp);
                ffma2(A1, gA.y, wp);
                ffma2(A2, gB.x, wp);
                ffma2(A3, gB.y, wp);
            }
        }
    }
    __syncthreads();                               // last tile's reads done

    // --- deterministic in-block reduction over the 8 lane_b partials ---
    float* sred = sG;                              // reuse smem (2048 floats needed)
    {
        ulonglong2* sp64 = reinterpret_cast<ulonglong2*>(sred);
        sp64[(a_local * 8 + lane_b) * 2 + 0] = make_ulonglong2(A0, A1);
        sp64[(a_local * 8 + lane_b) * 2 + 1] = make_ulonglong2(A2, A3);
    }
    __syncthreads();
    {
        int al = tid >> 3;          // 0..31
        int i  = tid & 7;           // 0..7
        float s = 0.0f;
#pragma unroll
        for (int lb = 0; lb < 8; ++lb)
            s += sred[(al * 8 + lb) * 8 + i];
        g_partial[((blockIdx.y * BATCH + z) * NPTS + (a0 + al)) * DOUT + i] = s;
    }
}

// ---------------------------------------------------------------------------
// Kernel 3: sum the SPLIT partials into the output (deterministic, no atomics)
// ---------------------------------------------------------------------------
__global__ __launch_bounds__(256)
void reduce_kernel(float* __restrict__ out)
{
    int t = blockIdx.x * blockDim.x + threadIdx.x;
    if (t < BATCH * NPTS * DOUT) {
        float s = 0.0f;
#pragma unroll
        for (int sp = 0; sp < SPLIT; ++sp)
            s += g_partial[sp * (BATCH * NPTS * DOUT) + t];
        out[t] = s;
    }
}

extern "C" void kernel_launch(void* const* d_in, const int* in_sizes, int n_in,
                              void* d_out, int out_size)
{
    const float* features = (const float*)d_in[0];   // [2,1024,8]
    const float* geometry = (const float*)d_in[1];   // [2,1024,3]
    const float* W        = (const float*)d_in[2];   // [32,8,8]
    const int*   n_norm   = (const int*)d_in[3];     // scalar
    float*       out      = (float*)d_out;           // [2,1024,8]

    prep_G_kernel<<<(BATCH * NPTS) / 32, 256>>>(features, W, n_norm);
    conv_kernel<<<dim3(NPTS / TILE_A, SPLIT, BATCH), 256>>>(geometry);
    reduce_kernel<<<(BATCH * NPTS * DOUT + 255) / 256, 256>>>(out);
}

// round 12
// speedup vs baseline: 1.8464x; 1.8260x over previous
#include <cuda_runtime.h>
#include <cuda_fp16.h>

// Convolution_22600117912286: continuous convolution with Gaussian radial basis.
// out[z,a,i] = (1/sqrt(n_norm)) * sum_b sum_c exp(-((d_ab - c*w)/w)^2) * G[z,b,c,i]
//   where G[z,b,c,i] = sum_j W[c,i,j] * features[z,b,j]
// Shapes: B=2, N=1024, D_IN=8, D_OUT=8, C=32, R_MAX=3.5, w=3.5/31.
//
// R11 changes vs R6 (conv is smem-crossbar bound, ~80K cyc of LDS):
//  - G stored fp16 (half the LDS bytes: 1 LDS.128 per tap instead of 2).
//  - 8-tap floor-anchored window (w0 = floor(u0-3), m in [3,4]): all taps
//    within dist 4, dropped terms <= exp(-16); ascending recurrence needs no
//    weight array and only 2 exps (+1 sqrt) per pair.
//  - prep reshaped: 128 blocks, __half2 stores.

#define BATCH   2
#define NPTS    1024
#define DIN     8
#define DOUT    8
#define NC      32
#define RMAXF   3.5f
#define TILE_A  32
#define SPLIT   8
#define B_TILE  16
#define KPAD    4
#define KROWS   (NC + 2 * KPAD)   // rows -4..35; pads stay zero
#define RSTRIDE 24                // halves per (b,k) row: 8 data + 16 pad = 48B
                                  // (48B stride => 8 bank-position classes tiling 32 banks)

// scratch (no allocations allowed -> __device__ globals)
__device__ __align__(16) __half2 g_Gh[BATCH * NPTS * NC * DOUT / 2];   // 1 MB
__device__ float g_partial[SPLIT * BATCH * NPTS * DOUT];               // 512 KB

// ---------------------------------------------------------------------------
// Kernel 1: G[z,b,c,i] = scale * sum_j W[c,i,j] * f[z,b,j], stored fp16.
// Block covers 16 zb rows; thread = (zb half, i-pair column). 128 blocks.
// ---------------------------------------------------------------------------
__global__ __launch_bounds__(256)
void prep_G_kernel(const float* __restrict__ feat,
                   const float* __restrict__ W,
                   const int* __restrict__ n_norm)
{
    __shared__ __align__(16) float sf[16 * DIN];

    const int tid = threadIdx.x;
    const int zb0 = blockIdx.x * 16;

    if (tid < 128) sf[tid] = feat[zb0 * DIN + tid];
    __syncthreads();

    const float scale = rsqrtf((float)(*n_norm));

    const int cp = tid & 127;        // column pair: cols 2cp, 2cp+1
    const int zh = tid >> 7;         // 0/1 -> zb rows 0..7 / 8..15

    const float4* Wv = reinterpret_cast<const float4*>(W + cp * 16);
    float4 wa0 = Wv[0], wb0 = Wv[1], wa1 = Wv[2], wb1 = Wv[3];
    wa0.x *= scale; wa0.y *= scale; wa0.z *= scale; wa0.w *= scale;
    wb0.x *= scale; wb0.y *= scale; wb0.z *= scale; wb0.w *= scale;
    wa1.x *= scale; wa1.y *= scale; wa1.z *= scale; wa1.w *= scale;
    wb1.x *= scale; wb1.y *= scale; wb1.z *= scale; wb1.w *= scale;

#pragma unroll
    for (int b = 0; b < 8; ++b) {
        const int zb_l = zh * 8 + b;
        float4 fa = *reinterpret_cast<const float4*>(&sf[zb_l * DIN]);
        float4 fb = *reinterpret_cast<const float4*>(&sf[zb_l * DIN + 4]);
        float s0 = wa0.x * fa.x;
        s0 = fmaf(wa0.y, fa.y, s0); s0 = fmaf(wa0.z, fa.z, s0); s0 = fmaf(wa0.w, fa.w, s0);
        s0 = fmaf(wb0.x, fb.x, s0); s0 = fmaf(wb0.y, fb.y, s0);
        s0 = fmaf(wb0.z, fb.z, s0); s0 = fmaf(wb0.w, fb.w, s0);
        float s1 = wa1.x * fa.x;
        s1 = fmaf(wa1.y, fa.y, s1); s1 = fmaf(wa1.z, fa.z, s1); s1 = fmaf(wa1.w, fa.w, s1);
        s1 = fmaf(wb1.x, fb.x, s1); s1 = fmaf(wb1.y, fb.y, s1);
        s1 = fmaf(wb1.z, fb.z, s1); s1 = fmaf(wb1.w, fb.w, s1);
        g_Gh[(size_t)(zb0 + zb_l) * 128 + cp] = __floats2half2_rn(s0, s1);
    }
}

// ---------------------------------------------------------------------------
// Kernel 2: main pairwise contraction.
// Block = (z, a-tile of 32, b-split of 128). Warp = 32 a's; lane_b = tid>>5.
// 8-tap window k = w0..w0+7 with w0 = floor(u0-3): m = u0-w0 in [3,4], all
// taps within dist 4 of u0; weights via ascending recurrence
//   v0 = exp(-m^2), r0 = exp(2m-1), v *= r, r *= exp(-2).
// Clamps: w0 <= 28 (taps <= 35, inside padded rows); m capped at 14 so
// v0 underflows to exact 0 for far pairs (true weights <= 3.7e-5 there).
// ---------------------------------------------------------------------------
__global__ __launch_bounds__(256)
void conv_kernel(const float* __restrict__ geom)
{
    __shared__ __align__(16) __half sGh[B_TILE * KROWS * RSTRIDE];  // 30 KB
    __shared__ float4 sgeo[B_TILE];

    const int tid     = threadIdx.x;
    const int z       = blockIdx.z;
    const int a0      = blockIdx.x * TILE_A;
    const int bsplit0 = blockIdx.y * (NPTS / SPLIT);
    const int a_local = tid & (TILE_A - 1);
    const int lane_b  = tid >> 5;                  // 0..7

    // zero the tile once (pad rows are never written afterwards)
    {
        uint4* sz = reinterpret_cast<uint4*>(sGh);
        const int NU = B_TILE * KROWS * RSTRIDE / 8;   // 1920 uint4
        for (int q = tid; q < NU; q += 256) sz[q] = make_uint4(0u, 0u, 0u, 0u);
    }

    const int   a  = a0 + a_local;
    const float ax = geom[(z * NPTS + a) * 3 + 0];
    const float ay = geom[(z * NPTS + a) * 3 + 1];
    const float az = geom[(z * NPTS + a) * 3 + 2];

    const float INV_W = (float)(NC - 1) / RMAXF;   // 31/3.5
    const float E2    = 0.13533528323661270f;      // exp(-2)

    float a0f = 0.f, a1f = 0.f, a2f = 0.f, a3f = 0.f;
    float a4f = 0.f, a5f = 0.f, a6f = 0.f, a7f = 0.f;

    const int NT = (NPTS / SPLIT) / B_TILE;        // 8 tiles
    for (int t = 0; t < NT; ++t) {
        const int bt = bsplit0 + t * B_TILE;
        __syncthreads();                           // protect sGh/sgeo

        if (tid < B_TILE) {
            const float* gp = geom + (size_t)(z * NPTS + bt + tid) * 3;
            sgeo[tid] = make_float4(gp[0], gp[1], gp[2], 0.f);
        }
        // stage G tile: 16b x 32k rows of 16B, coalesced gmem -> padded smem
        const uint4* src = reinterpret_cast<const uint4*>(g_Gh)
                         + (size_t)(z * NPTS + bt) * NC;      // 32 uint4 per b
        uint4* dst = reinterpret_cast<uint4*>(sGh);
#pragma unroll
        for (int it = 0; it < 2; ++it) {
            int q = tid + it * 256;                // 0..511
            uint4 v  = src[q];
            int   k  = q & (NC - 1);
            int   bl = q >> 5;
            dst[(bl * KROWS + k + KPAD) * 3] = v;  // 48B row stride
        }
        __syncthreads();

#pragma unroll
        for (int half = 0; half < 2; ++half) {
            const int bl = lane_b + half * 8;
            float4 gb = sgeo[bl];
            float dx = ax - gb.x, dy = ay - gb.y, dz = az - gb.z;
            float d2 = fmaf(dx, dx, fmaf(dy, dy, fmaf(dz, dz, 1e-12f)));
            float u0 = sqrtf(d2) * INV_W;          // distance in width units
            int   w0 = (int)floorf(u0 - 3.0f);     // >= -3 since u0 >= 0
            w0 = min(w0, 28);                      // taps stay <= row 35
            float m  = u0 - (float)w0;             // in [3,4] unless clamped
            float mc = fminf(m, 14.0f);            // v0 underflows to 0 beyond
            float v  = __expf(-mc * mc);
            float r  = __expf(fmaf(2.0f, mc, -1.0f));

            const uint4* gp = reinterpret_cast<const uint4*>(sGh)
                            + (bl * KROWS + w0 + KPAD) * 3;
#pragma unroll
            for (int j = 0; j < 8; ++j) {
                uint4 raw = gp[j * 3];
                float2 f0 = __half22float2(*reinterpret_cast<__half2*>(&raw.x));
                float2 f1 = __half22float2(*reinterpret_cast<__half2*>(&raw.y));
                float2 f2 = __half22float2(*reinterpret_cast<__half2*>(&raw.z));
                float2 f3 = __half22float2(*reinterpret_cast<__half2*>(&raw.w));
                a0f = fmaf(v, f0.x, a0f);  a1f = fmaf(v, f0.y, a1f);
                a2f = fmaf(v, f1.x, a2f);  a3f = fmaf(v, f1.y, a3f);
                a4f = fmaf(v, f2.x, a4f);  a5f = fmaf(v, f2.y, a5f);
                a6f = fmaf(v, f3.x, a6f);  a7f = fmaf(v, f3.y, a7f);
                v *= r;
                r *= E2;
            }
        }
    }
    __syncthreads();                               // last tile's reads done

    // deterministic in-block reduction over the 8 lane_b partials (reuse smem)
    float* sred = reinterpret_cast<float*>(sGh);   // 2048 floats needed
    {
        float4* sp = reinterpret_cast<float4*>(sred);
        sp[(a_local * 8 + lane_b) * 2 + 0] = make_float4(a0f, a1f, a2f, a3f);
        sp[(a_local * 8 + lane_b) * 2 + 1] = make_float4(a4f, a5f, a6f, a7f);
    }
    __syncthreads();
    {
        int al = tid >> 3;          // 0..31
        int i  = tid & 7;           // 0..7
        float s = 0.0f;
#pragma unroll
        for (int lb = 0; lb < 8; ++lb)
            s += sred[(al * 8 + lb) * 8 + i];
        g_partial[((blockIdx.y * BATCH + z) * NPTS + (a0 + al)) * DOUT + i] = s;
    }
}

// ---------------------------------------------------------------------------
// Kernel 3: sum the SPLIT partials into the output (deterministic, no atomics)
// ---------------------------------------------------------------------------
__global__ __launch_bounds__(256)
void reduce_kernel(float* __restrict__ out)
{
    int t = blockIdx.x * blockDim.x + threadIdx.x;
    if (t < BATCH * NPTS * DOUT) {
        float s = 0.0f;
#pragma unroll
        for (int sp = 0; sp < SPLIT; ++sp)
            s += g_partial[sp * (BATCH * NPTS * DOUT) + t];
        out[t] = s;
    }
}

extern "C" void kernel_launch(void* const* d_in, const int* in_sizes, int n_in,
                              void* d_out, int out_size)
{
    const float* features = (const float*)d_in[0];   // [2,1024,8]
    const float* geometry = (const float*)d_in[1];   // [2,1024,3]
    const float* W        = (const float*)d_in[2];   // [32,8,8]
    const int*   n_norm   = (const int*)d_in[3];     // scalar
    float*       out      = (float*)d_out;           // [2,1024,8]

    prep_G_kernel<<<(BATCH * NPTS) / 16, 256>>>(features, W, n_norm);
    conv_kernel<<<dim3(NPTS / TILE_A, SPLIT, BATCH), 256>>>(geometry);
    reduce_kernel<<<(BATCH * NPTS * DOUT + 255) / 256, 256>>>(out);
}

// round 13
// speedup vs baseline: 1.9923x; 1.0790x over previous
#include <cuda_runtime.h>
#include <cuda_fp16.h>

// Convolution_22600117912286: continuous convolution with Gaussian radial basis.
// out[z,a,i] = (1/sqrt(n_norm)) * sum_b sum_c exp(-((d_ab - c*w)/w)^2) * G[z,b,c,i]
//   where G[z,b,c,i] = sum_j W[c,i,j] * features[z,b,j]
// Shapes: B=2, N=1024, D_IN=8, D_OUT=8, C=32, R_MAX=3.5, w=3.5/31.
//
// R12 changes vs R11 (conv was smem-bank-conflict bound, kappa~2.5):
//  - Lane transpose: warp lanes = (p = a-subgroup 0..3, j = tap 0..7). Each
//    tap-LDS reads rows w0_p + j whose 48B-stride positions (x3 mod 8) form a
//    complete permutation per group -> provably conflict-free (kappa = 1).
//  - Distances computed once per 8 b's by all 32 lanes, broadcast via SHFL.
//    Weight = one direct per-lane __expf(-(m-j)^2); recurrence dependency gone.
//  - HFMA2 inner accumulation (4 HFMA2/tap), fp32 flush every 8 b's.
//  - Per-a accumulators reduced over taps with one end-of-kernel shfl butterfly
//    (smem block reduction removed).
//  - prep flattened: 1 thread per half2 output, 1024 blocks (was latency-bound).

#define BATCH   2
#define NPTS    1024
#define NC      32
#define RMAXF   3.5f
#define TILE_A  32
#define SPLIT   8
#define B_TILE  16
#define KPAD    4
#define KROWS   (NC + 2 * KPAD)   // rows -4..35 in k space; pads stay zero
#define RSTRIDE 24                // halves per (b,k) row: 8 data + 16 pad = 48B

// scratch (no allocations allowed -> __device__ globals)
__device__ __align__(16) __half2 g_Gh[BATCH * NPTS * NC * 4];   // 1 MB (half2 units)
__device__ float g_partial[SPLIT * BATCH * NPTS * 8];           // 512 KB

// ---------------------------------------------------------------------------
// Kernel 1: G[z,b,c,i] = scale * sum_j W[c,i,j] * f[z,b,j], stored fp16.
// One thread per half2 output (zb, cp): 262144 threads, 1024 blocks.
// ---------------------------------------------------------------------------
__global__ __launch_bounds__(256)
void prep_G_kernel(const float* __restrict__ feat,
                   const float* __restrict__ W,
                   const int* __restrict__ n_norm)
{
    const int gid = blockIdx.x * 256 + threadIdx.x;   // 0 .. 262143
    const int cp  = gid & 127;                        // column pair: cols 2cp, 2cp+1
    const int zb  = gid >> 7;

    const float scale = rsqrtf((float)(*n_norm));

    const float4* fv = reinterpret_cast<const float4*>(feat + zb * 8);
    float4 fa = __ldg(fv), fb = __ldg(fv + 1);

    const float4* Wv = reinterpret_cast<const float4*>(W + cp * 16);
    float4 wa0 = __ldg(Wv + 0), wb0 = __ldg(Wv + 1);
    float4 wa1 = __ldg(Wv + 2), wb1 = __ldg(Wv + 3);

    float s0 = wa0.x * fa.x;
    s0 = fmaf(wa0.y, fa.y, s0); s0 = fmaf(wa0.z, fa.z, s0); s0 = fmaf(wa0.w, fa.w, s0);
    s0 = fmaf(wb0.x, fb.x, s0); s0 = fmaf(wb0.y, fb.y, s0);
    s0 = fmaf(wb0.z, fb.z, s0); s0 = fmaf(wb0.w, fb.w, s0);
    float s1 = wa1.x * fa.x;
    s1 = fmaf(wa1.y, fa.y, s1); s1 = fmaf(wa1.z, fa.z, s1); s1 = fmaf(wa1.w, fa.w, s1);
    s1 = fmaf(wb1.x, fb.x, s1); s1 = fmaf(wb1.y, fb.y, s1);
    s1 = fmaf(wb1.z, fb.z, s1); s1 = fmaf(wb1.w, fb.w, s1);

    g_Gh[gid] = __floats2half2_rn(s0 * scale, s1 * scale);
}

// ---------------------------------------------------------------------------
// Kernel 2: main pairwise contraction (lane-transposed, conflict-free taps).
// Block = (z, a-tile of 32, b-split of 128). Warp owns 4 a's; lanes = (p, j).
// 8-tap window k = w0..w0+7, w0 = min(floor(u0-3), 28): every kept in-range
// tap is within 4 widths; dropped in-range terms <= exp(-9) relative weight
// hidden behind fp16 noise; k>31 taps read permanently-zero pad rows.
// ---------------------------------------------------------------------------
__global__ __launch_bounds__(256)
void conv_kernel(const float* __restrict__ geom)
{
    __shared__ __align__(16) __half sGh[B_TILE * KROWS * RSTRIDE];  // 30 KB
    __shared__ __align__(16) float  sgeo[B_TILE * 4];

    const int tid     = threadIdx.x;
    const int z       = blockIdx.z;
    const int a0      = blockIdx.x * TILE_A;
    const int bsplit0 = blockIdx.y * (NPTS / SPLIT);
    const int wid     = tid >> 5;              // 0..7
    const int lane    = tid & 31;
    const int p       = lane >> 3;             // a-subgroup 0..3
    const int j       = lane & 7;              // tap index 0..7
    const float jf    = (float)j;
    const int   joff  = j * (RSTRIDE * 2);     // tap byte offset (48B rows)

    // zero the tile once (pad rows are never written afterwards)
    {
        uint4* sz = reinterpret_cast<uint4*>(sGh);
        const int NU = B_TILE * KROWS * RSTRIDE / 8;   // 1920 uint4
        for (int q = tid; q < NU; q += 256) sz[q] = make_uint4(0u, 0u, 0u, 0u);
    }

    const int   a  = a0 + wid * 4 + p;         // this lane's output point
    const float ax = geom[(z * NPTS + a) * 3 + 0];
    const float ay = geom[(z * NPTS + a) * 3 + 1];
    const float az = geom[(z * NPTS + a) * 3 + 2];

    const float INV_W   = (float)(NC - 1) / RMAXF;     // 31/3.5
    const float NLOG2E  = -1.4426950408889634f;        // -log2(e)

    float acc0 = 0.f, acc1 = 0.f, acc2 = 0.f, acc3 = 0.f;
    float acc4 = 0.f, acc5 = 0.f, acc6 = 0.f, acc7 = 0.f;

    const int NT = (NPTS / SPLIT) / B_TILE;    // 8 tiles
    for (int t = 0; t < NT; ++t) {
        const int bt = bsplit0 + t * B_TILE;
        __syncthreads();                       // protect sGh/sgeo from last iter

        if (tid < B_TILE) {                    // stage geometry (scalar, in-bounds)
            const float* gp = geom + (size_t)(z * NPTS + bt + tid) * 3;
            sgeo[tid * 4 + 0] = gp[0];
            sgeo[tid * 4 + 1] = gp[1];
            sgeo[tid * 4 + 2] = gp[2];
        }
        // stage G tile: 16b x 32k rows of 16B, coalesced gmem -> padded smem
        const uint4* src = reinterpret_cast<const uint4*>(g_Gh)
                         + (size_t)(z * NPTS + bt) * NC;
        uint4* dst = reinterpret_cast<uint4*>(sGh);
#pragma unroll
        for (int it = 0; it < 2; ++it) {
            int q  = tid + it * 256;           // 0..511
            uint4 v  = src[q];
            int   k  = q & (NC - 1);
            int   bl = q >> 5;
            dst[(bl * KROWS + k + KPAD) * 3] = v;
        }
        __syncthreads();

#pragma unroll
        for (int r = 0; r < 2; ++r) {          // two groups of 8 b's
            // phase 1: lane (p, q=j) computes window params for (a_p, b_{r*8+q})
            const int bl = r * 8 + j;
            float bx = sgeo[bl * 4 + 0];
            float by = sgeo[bl * 4 + 1];
            float bz = sgeo[bl * 4 + 2];
            float dx = ax - bx, dy = ay - by, dz = az - bz;
            float d2 = fmaf(dx, dx, fmaf(dy, dy, fmaf(dz, dz, 1e-12f)));
            float u0 = sqrtf(d2) * INV_W;
            float w0f = fminf(floorf(u0 - 3.0f), 28.0f);   // >= -3, <= 28
            float m   = u0 - w0f;                          // window phase (may be big)
            int   w0i = (int)w0f;
            int   A   = (bl * KROWS + w0i + KPAD) * (RSTRIDE * 2);  // byte offset

            __half2 h2z = __float2half2_rn(0.0f);
            __half2 hc0 = h2z, hc1 = h2z, hc2 = h2z, hc3 = h2z;

#pragma unroll
            for (int bsub = 0; bsub < 8; ++bsub) {
                int   srcl = (lane & 24) + bsub;
                float mb = __shfl_sync(0xffffffffu, m, srcl);
                int   Ab = __shfl_sync(0xffffffffu, A, srcl);
                float dj = mb - jf;
                float w  = exp2f(dj * dj * NLOG2E);        // exp(-(m-j)^2)
                __half2 wh = __float2half2_rn(w);
                uint4 raw = *reinterpret_cast<const uint4*>(
                    reinterpret_cast<const char*>(sGh) + (Ab + joff));
                hc0 = __hfma2(*reinterpret_cast<__half2*>(&raw.x), wh, hc0);
                hc1 = __hfma2(*reinterpret_cast<__half2*>(&raw.y), wh, hc1);
                hc2 = __hfma2(*reinterpret_cast<__half2*>(&raw.z), wh, hc2);
                hc3 = __hfma2(*reinterpret_cast<__half2*>(&raw.w), wh, hc3);
            }
            // flush the 8-term fp16 partials into fp32 accumulators
            float2 f0 = __half22float2(hc0);
            float2 f1 = __half22float2(hc1);
            float2 f2 = __half22float2(hc2);
            float2 f3 = __half22float2(hc3);
            acc0 += f0.x; acc1 += f0.y; acc2 += f1.x; acc3 += f1.y;
            acc4 += f2.x; acc5 += f2.y; acc6 += f3.x; acc7 += f3.y;
        }
    }

    // reduce over the 8 tap-lanes of each a-subgroup (xor butterfly, lanes p*8+j)
#pragma unroll
    for (int st = 1; st < 8; st <<= 1) {
        acc0 += __shfl_xor_sync(0xffffffffu, acc0, st);
        acc1 += __shfl_xor_sync(0xffffffffu, acc1, st);
        acc2 += __shfl_xor_sync(0xffffffffu, acc2, st);
        acc3 += __shfl_xor_sync(0xffffffffu, acc3, st);
        acc4 += __shfl_xor_sync(0xffffffffu, acc4, st);
        acc5 += __shfl_xor_sync(0xffffffffu, acc5, st);
        acc6 += __shfl_xor_sync(0xffffffffu, acc6, st);
        acc7 += __shfl_xor_sync(0xffffffffu, acc7, st);
    }
    if (j == 0) {
        float* dst = g_partial
                   + ((size_t)(blockIdx.y * BATCH + z) * NPTS + a) * 8;
        *reinterpret_cast<float4*>(dst)     = make_float4(acc0, acc1, acc2, acc3);
        *reinterpret_cast<float4*>(dst + 4) = make_float4(acc4, acc5, acc6, acc7);
    }
}

// ---------------------------------------------------------------------------
// Kernel 3: sum the SPLIT partials into the output (deterministic, no atomics)
// ---------------------------------------------------------------------------
__global__ __launch_bounds__(256)
void reduce_kernel(float* __restrict__ out)
{
    int t = blockIdx.x * blockDim.x + threadIdx.x;
    if (t < BATCH * NPTS * 8) {
        float s = 0.0f;
#pragma unroll
        for (int sp = 0; sp < SPLIT; ++sp)
            s += g_partial[sp * (BATCH * NPTS * 8) + t];
        out[t] = s;
    }
}

extern "C" void kernel_launch(void* const* d_in, const int* in_sizes, int n_in,
                              void* d_out, int out_size)
{
    const float* features = (const float*)d_in[0];   // [2,1024,8]
    const float* geometry = (const float*)d_in[1];   // [2,1024,3]
    const float* W        = (const float*)d_in[2];   // [32,8,8]
    const int*   n_norm   = (const int*)d_in[3];     // scalar
    float*       out      = (float*)d_out;           // [2,1024,8]

    prep_G_kernel<<<(BATCH * NPTS * 128) / 256, 256>>>(features, W, n_norm);
    conv_kernel<<<dim3(NPTS / TILE_A, SPLIT, BATCH), 256>>>(geometry);
    reduce_kernel<<<(BATCH * NPTS * 8 + 255) / 256, 256>>>(out);
}